// round 8
// baseline (speedup 1.0000x reference)
#include <cuda_runtime.h>
#include <cuda_bf16.h>
#include <cstdint>

// Problem constants
#define BSZ 4
#define NS  1024
#define D   2048
#define H   16
#define DH  128
#define SEQ (BSZ*NS)          // 4096
#define E3  (3*D)             // 6144
#define SCALE 0.08838834764831845f   // DH^-0.5
#define NEG_BIAS (-1e9f)

// ---------------- scratch (global device arrays; no allocations) -------------
__device__ float g_qkv[SEQ * E3];                 // [4096, 6144] tf32-rounded
__device__ float g_S[(long)BSZ * H * NS * NS];    // [64, 1024, 1024]
__device__ float g_ctx[SEQ * D];                  // [4096, 2048] tf32-rounded
__device__ float g_xr[SEQ * D];                   // tf32-rounded x
__device__ float g_winr[E3 * D];                  // tf32-rounded w_in
__device__ float g_woutr[D * D];                  // tf32-rounded w_out

__device__ __forceinline__ uint32_t to_tf32(float x) {
    uint32_t r;
    asm("cvt.rna.tf32.f32 %0, %1;" : "=r"(r) : "f"(x));
    return r;
}
__device__ __forceinline__ float round_tf32f(float x) {
    return __uint_as_float(to_tf32(x));
}

// ---------------- elementwise tf32 pre-round ----------------------------------
__global__ __launch_bounds__(256)
void round_tf32_kernel(const float* __restrict__ in, float* __restrict__ out, long n4)
{
    long i = blockIdx.x * (long)blockDim.x + threadIdx.x;
    long stride = (long)gridDim.x * blockDim.x;
    for (; i < n4; i += stride) {
        float4 v = ((const float4*)in)[i];
        v.x = round_tf32f(v.x); v.y = round_tf32f(v.y);
        v.z = round_tf32f(v.z); v.w = round_tf32f(v.w);
        ((float4*)out)[i] = v;
    }
}

// ---------------- tf32 tensor-core GEMM, cp.async 3-stage pipeline ------------
// Inputs must already be tf32-rounded. No cvt in the mainloop.
// C[M,N] = A[M,K] * B
//   A: K-contiguous, leading dim lda
//   B_NN=false: B is [N,K] K-contiguous (NT), ldb = row stride
//   B_NN=true : B is [K,N] N-contiguous (NN), ldb = row stride
// EPI: 0 plain, 1 +bias[col], 2 (acc + ids[col]*-1e9)*scale
// ROUND: round outputs to tf32 (for tensors consumed by later GEMMs)
#define BM 128
#define BN 128
#define BK 32
#define STAGES 3
#define STAGE_FLOATS 8192          // A: 128*32, B: 4096 (either layout)
#define STAGE_BYTES (STAGE_FLOATS * 4)
#define SMEM_BYTES (STAGES * STAGE_BYTES)   // 96 KB

template<bool B_NN, int EPI, bool ROUND>
__global__ __launch_bounds__(256)
void tgemm_kernel(const float* __restrict__ A,
                  const float* __restrict__ B,
                  float* __restrict__ C,
                  int K, int lda, int ldb, int ldc,
                  long aOuter, long aInner,
                  long bOuter, long bInner,
                  long cOuter, long cInner,
                  int hdiv,
                  const float* __restrict__ bias,
                  const int* __restrict__ ids, int idsStride)
{
    extern __shared__ float sm[];
    const uint32_t smBase = (uint32_t)__cvta_generic_to_shared(sm);

    const int z  = blockIdx.z;
    const int bo = z / hdiv;
    const int hi = z - bo * hdiv;
    A += (long)bo * aOuter + (long)hi * aInner;
    B += (long)bo * bOuter + (long)hi * bInner;
    C += (long)bo * cOuter + (long)hi * cInner;
    if (EPI == 2) ids += (long)bo * idsStride;

    const int tid  = threadIdx.x;
    const int lane = tid & 31;
    const int wid  = tid >> 5;
    const int g    = lane >> 2;     // 0..7
    const int i4   = lane & 3;      // 0..3
    const int warp_m = wid >> 2;    // 0..1  (64 rows)
    const int warp_n = wid & 3;     // 0..3  (32 cols)

    const int m0 = blockIdx.y * BM;
    const int n0 = blockIdx.x * BN;

    float acc[4][4][4];
    #pragma unroll
    for (int a = 0; a < 4; a++)
        #pragma unroll
        for (int b = 0; b < 4; b++)
            #pragma unroll
            for (int c = 0; c < 4; c++)
                acc[a][b][c] = 0.f;

    const int nK = K / BK;

    // ---- persistent producer state: pointers advance by BK per produced tile.
    // Swizzle: A / NT-B element (row, k) at row*32 + (((k>>2) ^ (row&7))<<2) + (k&3)
    //          NN-B  element (k, n)  at k*128 + (((n>>2) ^ (k&7))<<2) + (n&3)
    const float* aSrc[4];
    const float* bSrc[4];
    uint32_t dAoff[4], dBoff[4];   // byte offsets within a stage
    #pragma unroll
    for (int u = 0; u < 4; u++) {
        int slot = tid + u * 256;
        int row  = slot >> 3;
        int c4   = slot & 7;
        aSrc[u]  = A + (long)(m0 + row) * lda + c4 * 4;
        dAoff[u] = (row * 32 + ((c4 ^ (row & 7)) << 2)) * 4;
        if (!B_NN) {
            bSrc[u]  = B + (long)(n0 + row) * ldb + c4 * 4;
            dBoff[u] = 16384 + (row * 32 + ((c4 ^ (row & 7)) << 2)) * 4;
        } else {
            int kr = slot >> 5;      // 0..31
            int n4 = slot & 31;      // 0..31
            bSrc[u]  = B + (long)kr * ldb + n0 + n4 * 4;
            dBoff[u] = 16384 + (kr * 128 + ((n4 ^ (kr & 7)) << 2)) * 4;
        }
    }
    const long bAdv = B_NN ? (long)BK * ldb : BK;

    auto produce = [&](int st) {
        uint32_t base = smBase + st * STAGE_BYTES;
        #pragma unroll
        for (int u = 0; u < 4; u++) {
            asm volatile("cp.async.cg.shared.global [%0], [%1], 16;\n"
                         :: "r"(base + dAoff[u]), "l"(aSrc[u]));
            asm volatile("cp.async.cg.shared.global [%0], [%1], 16;\n"
                         :: "r"(base + dBoff[u]), "l"(bSrc[u]));
            aSrc[u] += BK;
            bSrc[u] += bAdv;
        }
    };

    uint32_t af[2][4][4], bf[2][4][2];

    auto load_frags = [&](int st, int ks, int p) {
        const uint32_t* As = (const uint32_t*)(sm + st * STAGE_FLOATS);
        const uint32_t* Bs = As + 4096;
        const int c0 = (((2 * ks)     ^ g) << 2) + i4;
        const int c1 = (((2 * ks + 1) ^ g) << 2) + i4;
        #pragma unroll
        for (int mt = 0; mt < 4; mt++) {
            int r = warp_m * 64 + mt * 16 + g;
            af[p][mt][0] = As[r * 32 + c0];
            af[p][mt][1] = As[(r + 8) * 32 + c0];
            af[p][mt][2] = As[r * 32 + c1];
            af[p][mt][3] = As[(r + 8) * 32 + c1];
        }
        if (!B_NN) {
            #pragma unroll
            for (int nt = 0; nt < 4; nt++) {
                int rn = warp_n * 32 + nt * 8 + g;
                bf[p][nt][0] = Bs[rn * 32 + c0];
                bf[p][nt][1] = Bs[rn * 32 + c1];
            }
        } else {
            #pragma unroll
            for (int nt = 0; nt < 4; nt++) {
                int n  = warp_n * 32 + nt * 8 + g;
                int ng = n >> 2, nw = n & 3;
                bf[p][nt][0] = Bs[(8 * ks + i4) * 128 + ((ng ^ i4) << 2) + nw];
                bf[p][nt][1] = Bs[(8 * ks + i4 + 4) * 128 + ((ng ^ (i4 + 4)) << 2) + nw];
            }
        }
    };

    auto mma_step = [&](int p) {
        #pragma unroll
        for (int mt = 0; mt < 4; mt++)
            #pragma unroll
            for (int nt = 0; nt < 4; nt++) {
                float* c = acc[mt][nt];
                asm volatile(
                    "mma.sync.aligned.m16n8k8.row.col.f32.tf32.tf32.f32 "
                    "{%0,%1,%2,%3}, {%4,%5,%6,%7}, {%8,%9}, {%0,%1,%2,%3};\n"
                    : "+f"(c[0]), "+f"(c[1]), "+f"(c[2]), "+f"(c[3])
                    : "r"(af[p][mt][0]), "r"(af[p][mt][1]),
                      "r"(af[p][mt][2]), "r"(af[p][mt][3]),
                      "r"(bf[p][nt][0]), "r"(bf[p][nt][1]));
            }
    };

    // prologue: stages 0 and 1 in flight
    produce(0);
    asm volatile("cp.async.commit_group;\n" ::: "memory");
    if (nK > 1) produce(1);
    asm volatile("cp.async.commit_group;\n" ::: "memory");

    // single __syncthreads per iteration:
    //   sync orders (a) tile kt visibility to all threads, (b) compute(kt-1)
    //   completion before produce(kt+2) overwrites stage (kt+2)%3 == (kt-1)%3.
    for (int kt = 0; kt < nK; kt++) {
        asm volatile("cp.async.wait_group 1;\n" ::: "memory");
        __syncthreads();
        if (kt + 2 < nK) produce((kt + 2) % STAGES);
        asm volatile("cp.async.commit_group;\n" ::: "memory");

        const int st = kt % STAGES;
        load_frags(st, 0, 0);
        #pragma unroll
        for (int ks = 0; ks < 4; ks++) {
            if (ks < 3) load_frags(st, ks + 1, (ks + 1) & 1);
            mma_step(ks & 1);
        }
    }

    // epilogue: c0 {g, 2i}, c1 {g, 2i+1}, c2 {g+8, 2i}, c3 {g+8, 2i+1}
    #pragma unroll
    for (int mt = 0; mt < 4; mt++) {
        int r0 = m0 + warp_m * 64 + mt * 16 + g;
        int r1 = r0 + 8;
        #pragma unroll
        for (int nt = 0; nt < 4; nt++) {
            int col = n0 + warp_n * 32 + nt * 8 + 2 * i4;
            float v0 = acc[mt][nt][0], v1 = acc[mt][nt][1];
            float v2 = acc[mt][nt][2], v3 = acc[mt][nt][3];
            if (EPI == 1) {
                float b0 = bias[col], b1 = bias[col + 1];
                v0 += b0; v1 += b1; v2 += b0; v3 += b1;
            }
            if (EPI == 2) {
                float bb0 = (float)ids[col]     * NEG_BIAS;
                float bb1 = (float)ids[col + 1] * NEG_BIAS;
                v0 = (v0 + bb0) * SCALE; v1 = (v1 + bb1) * SCALE;
                v2 = (v2 + bb0) * SCALE; v3 = (v3 + bb1) * SCALE;
            }
            if (ROUND) {
                v0 = round_tf32f(v0); v1 = round_tf32f(v1);
                v2 = round_tf32f(v2); v3 = round_tf32f(v3);
            }
            *(float2*)(C + (long)r0 * ldc + col) = make_float2(v0, v1);
            *(float2*)(C + (long)r1 * ldc + col) = make_float2(v2, v3);
        }
    }
}

// ---------------- row softmax over 1024 columns (tf32-rounded probs) ----------
__global__ __launch_bounds__(256)
void softmax_kernel(float* __restrict__ S)
{
    const long row = blockIdx.x;
    float* p = S + row * (long)NS;
    const int tid = threadIdx.x;
    const int lane = tid & 31, wid = tid >> 5;

    float4 v = ((const float4*)p)[tid];

    float mx = fmaxf(fmaxf(v.x, v.y), fmaxf(v.z, v.w));
    #pragma unroll
    for (int o = 16; o; o >>= 1) mx = fmaxf(mx, __shfl_xor_sync(0xffffffffu, mx, o));
    __shared__ float red[8];
    if (lane == 0) red[wid] = mx;
    __syncthreads();
    float m = red[0];
    #pragma unroll
    for (int i = 1; i < 8; i++) m = fmaxf(m, red[i]);

    float4 e;
    e.x = __expf(v.x - m);
    e.y = __expf(v.y - m);
    e.z = __expf(v.z - m);
    e.w = __expf(v.w - m);

    float s = e.x + e.y + e.z + e.w;
    #pragma unroll
    for (int o = 16; o; o >>= 1) s += __shfl_xor_sync(0xffffffffu, s, o);
    __syncthreads();
    if (lane == 0) red[wid] = s;
    __syncthreads();
    float tot = red[0];
    #pragma unroll
    for (int i = 1; i < 8; i++) tot += red[i];

    float inv = 1.0f / tot;
    e.x = round_tf32f(e.x * inv);
    e.y = round_tf32f(e.y * inv);
    e.z = round_tf32f(e.z * inv);
    e.w = round_tf32f(e.w * inv);
    ((float4*)p)[tid] = e;
}

// ---------------- launch ------------------------------------------------------
extern "C" void kernel_launch(void* const* d_in, const int* in_sizes, int n_in,
                              void* d_out, int out_size)
{
    const float* x     = (const float*)d_in[0];   // [4,1024,2048]
    const int*   ids   = (const int*)  d_in[1];   // [4,1024]
    const float* w_in  = (const float*)d_in[2];   // [6144,2048]
    const float* w_out = (const float*)d_in[3];   // [2048,2048]
    const float* b_out = (const float*)d_in[4];   // [2048]
    float* out = (float*)d_out;                   // [4,1024,2048]

    void *p_qkv, *p_S, *p_ctx, *p_xr, *p_winr, *p_woutr;
    cudaGetSymbolAddress(&p_qkv,  g_qkv);
    cudaGetSymbolAddress(&p_S,    g_S);
    cudaGetSymbolAddress(&p_ctx,  g_ctx);
    cudaGetSymbolAddress(&p_xr,   g_xr);
    cudaGetSymbolAddress(&p_winr, g_winr);
    cudaGetSymbolAddress(&p_woutr,g_woutr);
    float* qkv   = (float*)p_qkv;
    float* S     = (float*)p_S;
    float* ctx   = (float*)p_ctx;
    float* xr    = (float*)p_xr;
    float* winr  = (float*)p_winr;
    float* woutr = (float*)p_woutr;

    cudaFuncSetAttribute(tgemm_kernel<false, 0, true>,
                         cudaFuncAttributeMaxDynamicSharedMemorySize, SMEM_BYTES);
    cudaFuncSetAttribute(tgemm_kernel<false, 1, false>,
                         cudaFuncAttributeMaxDynamicSharedMemorySize, SMEM_BYTES);
    cudaFuncSetAttribute(tgemm_kernel<false, 2, false>,
                         cudaFuncAttributeMaxDynamicSharedMemorySize, SMEM_BYTES);
    cudaFuncSetAttribute(tgemm_kernel<true, 0, true>,
                         cudaFuncAttributeMaxDynamicSharedMemorySize, SMEM_BYTES);

    // K0: pre-round x, w_in, w_out to tf32
    round_tf32_kernel<<<512, 256>>>(x,     xr,    (long)SEQ * D / 4);
    round_tf32_kernel<<<512, 256>>>(w_in,  winr,  (long)E3 * D / 4);
    round_tf32_kernel<<<512, 256>>>(w_out, woutr, (long)D * D / 4);

    // K1: QKV = x @ w_in^T   [4096,6144] = [4096,2048] x [6144,2048]^T  (round out)
    tgemm_kernel<false, 0, true><<<dim3(E3 / BN, SEQ / BM, 1), 256, SMEM_BYTES>>>(
        xr, winr, qkv, D, D, D, E3,
        0, 0, 0, 0, 0, 0, 1, nullptr, nullptr, 0);

    // K2: S[b,h] = (Q K^T + mask) * scale   batched 64x
    tgemm_kernel<false, 2, false><<<dim3(NS / BN, NS / BM, BSZ * H), 256, SMEM_BYTES>>>(
        qkv, qkv + D, S,
        DH, E3, E3, NS,
        (long)NS * E3, DH,
        (long)NS * E3, DH,
        (long)H * NS * NS, (long)NS * NS,
        H, nullptr, ids, NS);

    // K3: row softmax (rounds probs to tf32)
    softmax_kernel<<<BSZ * H * NS, 256>>>(S);

    // K4: ctx[b,h] = P @ V   batched 64x  (round out)
    tgemm_kernel<true, 0, true><<<dim3(DH / BN, NS / BM, BSZ * H), 256, SMEM_BYTES>>>(
        S, qkv + 2 * D, ctx,
        NS, NS, E3, D,
        (long)H * NS * NS, (long)NS * NS,
        (long)NS * E3, DH,
        (long)NS * D, DH,
        H, nullptr, nullptr, 0);

    // K5: out = ctx @ w_out^T + b_out   [4096,2048] = [4096,2048] x [2048,2048]^T
    tgemm_kernel<false, 1, false><<<dim3(D / BN, SEQ / BM, 1), 256, SMEM_BYTES>>>(
        ctx, woutr, out, D, D, D, D,
        0, 0, 0, 0, 0, 0, 1, b_out, nullptr, 0);
}

// round 9
// speedup vs baseline: 1.0703x; 1.0703x over previous
#include <cuda_runtime.h>
#include <cuda_bf16.h>
#include <cstdint>

// Problem constants
#define BSZ 4
#define NS  1024
#define D   2048
#define H   16
#define DH  128
#define SEQ (BSZ*NS)          // 4096
#define E3  (3*D)             // 6144
#define SCALE 0.08838834764831845f   // DH^-0.5
#define NEG_BIAS (-1e9f)

// ---------------- scratch (global device arrays; no allocations) -------------
__device__ float g_qkv[SEQ * E3];                 // [4096, 6144] tf32-rounded
__device__ float g_ctx[SEQ * D];                  // [4096, 2048] tf32-rounded
__device__ float g_xr[SEQ * D];                   // tf32-rounded x
__device__ float g_winr[E3 * D];                  // tf32-rounded w_in
__device__ float g_woutr[D * D];                  // tf32-rounded w_out

__device__ __forceinline__ uint32_t to_tf32(float x) {
    uint32_t r;
    asm("cvt.rna.tf32.f32 %0, %1;" : "=r"(r) : "f"(x));
    return r;
}
__device__ __forceinline__ float round_tf32f(float x) {
    return __uint_as_float(to_tf32(x));
}

// ---------------- elementwise tf32 pre-round ----------------------------------
__global__ __launch_bounds__(256)
void round_tf32_kernel(const float* __restrict__ in, float* __restrict__ out, long n4)
{
    long i = blockIdx.x * (long)blockDim.x + threadIdx.x;
    long stride = (long)gridDim.x * blockDim.x;
    for (; i < n4; i += stride) {
        float4 v = ((const float4*)in)[i];
        v.x = round_tf32f(v.x); v.y = round_tf32f(v.y);
        v.z = round_tf32f(v.z); v.w = round_tf32f(v.w);
        ((float4*)out)[i] = v;
    }
}

// ---------------- tf32 tensor-core GEMM, cp.async 3-stage pipeline ------------
// (R7 body — proven 128 regs / 2 CTAs per SM; pinned via launch bounds.)
// C[M,N] = A[M,K] * B, A K-contiguous; B is [N,K] K-contiguous (NT).
// EPI: 0 plain, 1 +bias[col]. ROUND: tf32-round outputs.
#define BM 128
#define BN 128
#define BK 32
#define STAGES 3
#define STAGE_FLOATS 8192
#define SMEM_BYTES (STAGES * STAGE_FLOATS * 4)   // 96 KB

template<int EPI, bool ROUND>
__global__ __launch_bounds__(256, 2)
void tgemm_kernel(const float* __restrict__ A,
                  const float* __restrict__ B,
                  float* __restrict__ C,
                  int K, int lda, int ldb, int ldc,
                  const float* __restrict__ bias)
{
    extern __shared__ float sm[];

    const int tid  = threadIdx.x;
    const int lane = tid & 31;
    const int wid  = tid >> 5;
    const int g    = lane >> 2;
    const int i4   = lane & 3;
    const int warp_m = wid >> 2;
    const int warp_n = wid & 3;

    const int m0 = blockIdx.y * BM;
    const int n0 = blockIdx.x * BN;

    float acc[4][4][4];
    #pragma unroll
    for (int a = 0; a < 4; a++)
        #pragma unroll
        for (int b = 0; b < 4; b++)
            #pragma unroll
            for (int c = 0; c < 4; c++)
                acc[a][b][c] = 0.f;

    const int nK = K / BK;

    auto produce = [&](int st, int k0) {
        float* As = sm + st * STAGE_FLOATS;
        float* Bs = As + 4096;
        #pragma unroll
        for (int u = 0; u < 4; u++) {
            int slot = tid + u * 256;
            int row  = slot >> 3;
            int c4   = slot & 7;
            const float* srcA = A + (long)(m0 + row) * lda + k0 + c4 * 4;
            uint32_t dA = (uint32_t)__cvta_generic_to_shared(
                As + row * 32 + ((c4 ^ (row & 7)) << 2));
            asm volatile("cp.async.cg.shared.global [%0], [%1], 16;\n"
                         :: "r"(dA), "l"(srcA));
            const float* srcB = B + (long)(n0 + row) * ldb + k0 + c4 * 4;
            uint32_t dB = (uint32_t)__cvta_generic_to_shared(
                Bs + row * 32 + ((c4 ^ (row & 7)) << 2));
            asm volatile("cp.async.cg.shared.global [%0], [%1], 16;\n"
                         :: "r"(dB), "l"(srcB));
        }
    };

    uint32_t af[2][4][4], bf[2][4][2];

    auto load_frags = [&](int st, int ks, int p) {
        const uint32_t* As = (const uint32_t*)(sm + st * STAGE_FLOATS);
        const uint32_t* Bs = As + 4096;
        const int c0 = (((2 * ks)     ^ g) << 2) + i4;
        const int c1 = (((2 * ks + 1) ^ g) << 2) + i4;
        #pragma unroll
        for (int mt = 0; mt < 4; mt++) {
            int r = warp_m * 64 + mt * 16 + g;
            af[p][mt][0] = As[r * 32 + c0];
            af[p][mt][1] = As[(r + 8) * 32 + c0];
            af[p][mt][2] = As[r * 32 + c1];
            af[p][mt][3] = As[(r + 8) * 32 + c1];
        }
        #pragma unroll
        for (int nt = 0; nt < 4; nt++) {
            int rn = warp_n * 32 + nt * 8 + g;
            bf[p][nt][0] = Bs[rn * 32 + c0];
            bf[p][nt][1] = Bs[rn * 32 + c1];
        }
    };

    auto mma_step = [&](int p) {
        #pragma unroll
        for (int mt = 0; mt < 4; mt++)
            #pragma unroll
            for (int nt = 0; nt < 4; nt++) {
                float* c = acc[mt][nt];
                asm volatile(
                    "mma.sync.aligned.m16n8k8.row.col.f32.tf32.tf32.f32 "
                    "{%0,%1,%2,%3}, {%4,%5,%6,%7}, {%8,%9}, {%0,%1,%2,%3};\n"
                    : "+f"(c[0]), "+f"(c[1]), "+f"(c[2]), "+f"(c[3])
                    : "r"(af[p][mt][0]), "r"(af[p][mt][1]),
                      "r"(af[p][mt][2]), "r"(af[p][mt][3]),
                      "r"(bf[p][nt][0]), "r"(bf[p][nt][1]));
            }
    };

    produce(0, 0);
    asm volatile("cp.async.commit_group;\n" ::: "memory");
    if (nK > 1) produce(1, BK);
    asm volatile("cp.async.commit_group;\n" ::: "memory");

    for (int kt = 0; kt < nK; kt++) {
        asm volatile("cp.async.wait_group 1;\n" ::: "memory");
        __syncthreads();
        if (kt + 2 < nK) produce((kt + 2) % STAGES, (kt + 2) * BK);
        asm volatile("cp.async.commit_group;\n" ::: "memory");

        const int st = kt % STAGES;
        load_frags(st, 0, 0);
        #pragma unroll
        for (int ks = 0; ks < 4; ks++) {
            if (ks < 3) load_frags(st, ks + 1, (ks + 1) & 1);
            mma_step(ks & 1);
        }
        if (kt + 1 < nK) __syncthreads();
    }

    #pragma unroll
    for (int mt = 0; mt < 4; mt++) {
        int r0 = m0 + warp_m * 64 + mt * 16 + g;
        int r1 = r0 + 8;
        #pragma unroll
        for (int nt = 0; nt < 4; nt++) {
            int col = n0 + warp_n * 32 + nt * 8 + 2 * i4;
            float v0 = acc[mt][nt][0], v1 = acc[mt][nt][1];
            float v2 = acc[mt][nt][2], v3 = acc[mt][nt][3];
            if (EPI == 1) {
                float b0 = bias[col], b1 = bias[col + 1];
                v0 += b0; v1 += b1; v2 += b0; v3 += b1;
            }
            if (ROUND) {
                v0 = round_tf32f(v0); v1 = round_tf32f(v1);
                v2 = round_tf32f(v2); v3 = round_tf32f(v3);
            }
            *(float2*)(C + (long)r0 * ldc + col) = make_float2(v0, v1);
            *(float2*)(C + (long)r1 * ldc + col) = make_float2(v2, v3);
        }
    }
}

// ---------------- fused flash attention ---------------------------------------
// One CTA = 128 Q rows of one (b, h). Streams K/V in 128-key blocks.
// smem: Q 64KB + K 64KB + V 64KB + bias 512B
#define FL_SMEM_BYTES ((3 * 16384 + 128) * 4)

__global__ __launch_bounds__(256)
void flash_kernel(const float* __restrict__ qkv,
                  const int* __restrict__ ids,
                  float* __restrict__ ctx)
{
    extern __shared__ float sm[];
    float* sQ = sm;
    float* sK = sm + 16384;
    float* sV = sm + 32768;
    float* sBias = sm + 49152;
    const uint32_t* sQu = (const uint32_t*)sQ;
    const uint32_t* sKu = (const uint32_t*)sK;
    const uint32_t* sVu = (const uint32_t*)sV;

    const int qb = blockIdx.x;        // 0..7
    const int z  = blockIdx.y;        // 0..63
    const int b  = z >> 4;
    const int h  = z & 15;

    const int tid  = threadIdx.x;
    const int lane = tid & 31;
    const int w    = tid >> 5;        // warp 0..7, owns q rows w*16..w*16+15
    const int g    = lane >> 2;
    const int i4   = lane & 3;

    const float* Qsrc = qkv + ((long)(b * NS + qb * 128)) * E3 + h * DH;
    const float* Ksrc = qkv + ((long)b * NS) * E3 + D + h * DH;
    const float* Vsrc = qkv + ((long)b * NS) * E3 + 2 * D + h * DH;

    const uint32_t sQb = (uint32_t)__cvta_generic_to_shared(sQ);
    const uint32_t sKb = (uint32_t)__cvta_generic_to_shared(sK);
    const uint32_t sVb = (uint32_t)__cvta_generic_to_shared(sV);

    // 128x128 f32 tile load, XOR swizzle: (r,c) -> r*128 + ((c4 ^ (r&7))<<2) + (c&3)
    auto tile_load = [&](uint32_t dstBase, const float* src) {
        #pragma unroll
        for (int it = 0; it < 16; it++) {
            int slot = tid + it * 256;
            int r  = slot >> 5;
            int c4 = slot & 31;
            const float* s = src + (long)r * E3 + c4 * 4;
            uint32_t d = dstBase + (r * 128 + ((c4 ^ (r & 7)) << 2)) * 4;
            asm volatile("cp.async.cg.shared.global [%0], [%1], 16;\n"
                         :: "r"(d), "l"(s));
        }
    };

    tile_load(sQb, Qsrc);
    asm volatile("cp.async.commit_group;\n" ::: "memory");
    tile_load(sKb, Ksrc);
    asm volatile("cp.async.commit_group;\n" ::: "memory");

    float o[16][4];
    #pragma unroll
    for (int nt = 0; nt < 16; nt++)
        #pragma unroll
        for (int c = 0; c < 4; c++) o[nt][c] = 0.f;
    float m0 = -1e30f, m1 = -1e30f, l0 = 0.f, l1 = 0.f;

    const int rA = w * 16 + g;
    const int srcLow  = (lane & ~3) | (i4 >> 1);
    const int srcHigh = srcLow + 2;

    for (int j = 0; j < 8; j++) {
        asm volatile("cp.async.wait_group 0;\n" ::: "memory");
        __syncthreads();
        if (tid < 128)
            sBias[tid] = (float)ids[b * NS + j * 128 + tid] * NEG_BIAS;
        tile_load(sVb, Vsrc + (long)j * 128 * E3);
        asm volatile("cp.async.commit_group;\n" ::: "memory");

        // ---- S = Q K^T for this key block
        float sacc[16][4];
        #pragma unroll
        for (int nt = 0; nt < 16; nt++)
            #pragma unroll
            for (int c = 0; c < 4; c++) sacc[nt][c] = 0.f;

        #pragma unroll
        for (int ks = 0; ks < 16; ks++) {
            const int c0 = (((2 * ks)     ^ g) << 2) + i4;
            const int c1 = (((2 * ks + 1) ^ g) << 2) + i4;
            uint32_t a0 = sQu[rA * 128 + c0];
            uint32_t a1 = sQu[(rA + 8) * 128 + c0];
            uint32_t a2 = sQu[rA * 128 + c1];
            uint32_t a3 = sQu[(rA + 8) * 128 + c1];
            #pragma unroll
            for (int nt = 0; nt < 16; nt++) {
                uint32_t b0 = sKu[(nt * 8 + g) * 128 + c0];
                uint32_t b1 = sKu[(nt * 8 + g) * 128 + c1];
                float* c = sacc[nt];
                asm volatile(
                    "mma.sync.aligned.m16n8k8.row.col.f32.tf32.tf32.f32 "
                    "{%0,%1,%2,%3}, {%4,%5,%6,%7}, {%8,%9}, {%0,%1,%2,%3};\n"
                    : "+f"(c[0]), "+f"(c[1]), "+f"(c[2]), "+f"(c[3])
                    : "r"(a0), "r"(a1), "r"(a2), "r"(a3), "r"(b0), "r"(b1));
            }
        }

        asm volatile("cp.async.wait_group 0;\n" ::: "memory");
        __syncthreads();                       // V ready, bias visible, sK free
        if (j + 1 < 8) {
            tile_load(sKb, Ksrc + (long)(j + 1) * 128 * E3);
            asm volatile("cp.async.commit_group;\n" ::: "memory");
        }

        // ---- online softmax (rows g and g+8 of this warp's tile)
        float rmax0 = -1e30f, rmax1 = -1e30f;
        #pragma unroll
        for (int nt = 0; nt < 16; nt++) {
            int c = nt * 8 + 2 * i4;
            float bb0 = sBias[c], bb1 = sBias[c + 1];
            sacc[nt][0] = (sacc[nt][0] + bb0) * SCALE;
            sacc[nt][1] = (sacc[nt][1] + bb1) * SCALE;
            sacc[nt][2] = (sacc[nt][2] + bb0) * SCALE;
            sacc[nt][3] = (sacc[nt][3] + bb1) * SCALE;
            rmax0 = fmaxf(rmax0, fmaxf(sacc[nt][0], sacc[nt][1]));
            rmax1 = fmaxf(rmax1, fmaxf(sacc[nt][2], sacc[nt][3]));
        }
        rmax0 = fmaxf(rmax0, __shfl_xor_sync(0xffffffffu, rmax0, 1));
        rmax0 = fmaxf(rmax0, __shfl_xor_sync(0xffffffffu, rmax0, 2));
        rmax1 = fmaxf(rmax1, __shfl_xor_sync(0xffffffffu, rmax1, 1));
        rmax1 = fmaxf(rmax1, __shfl_xor_sync(0xffffffffu, rmax1, 2));

        float mn0 = fmaxf(m0, rmax0), mn1 = fmaxf(m1, rmax1);
        float corr0 = __expf(m0 - mn0), corr1 = __expf(m1 - mn1);
        m0 = mn0; m1 = mn1;

        float rs0 = 0.f, rs1 = 0.f;
        #pragma unroll
        for (int nt = 0; nt < 16; nt++) {
            float p0 = round_tf32f(__expf(sacc[nt][0] - mn0));
            float p1 = round_tf32f(__expf(sacc[nt][1] - mn0));
            float p2 = round_tf32f(__expf(sacc[nt][2] - mn1));
            float p3 = round_tf32f(__expf(sacc[nt][3] - mn1));
            sacc[nt][0] = p0; sacc[nt][1] = p1;
            sacc[nt][2] = p2; sacc[nt][3] = p3;
            rs0 += p0 + p1; rs1 += p2 + p3;
        }
        rs0 += __shfl_xor_sync(0xffffffffu, rs0, 1);
        rs0 += __shfl_xor_sync(0xffffffffu, rs0, 2);
        rs1 += __shfl_xor_sync(0xffffffffu, rs1, 1);
        rs1 += __shfl_xor_sync(0xffffffffu, rs1, 2);
        l0 = l0 * corr0 + rs0;
        l1 = l1 * corr1 + rs1;

        #pragma unroll
        for (int nt = 0; nt < 16; nt++) {
            o[nt][0] *= corr0; o[nt][1] *= corr0;
            o[nt][2] *= corr1; o[nt][3] *= corr1;
        }

        // ---- O += P V  (A-frags from acc via quad shuffles)
        #pragma unroll
        for (int ks = 0; ks < 16; ks++) {
            float c0 = sacc[ks][0], c1 = sacc[ks][1];
            float c2 = sacc[ks][2], c3 = sacc[ks][3];
            float tA, tB;
            tA = __shfl_sync(0xffffffffu, c0, srcLow);
            tB = __shfl_sync(0xffffffffu, c1, srcLow);
            uint32_t a0 = __float_as_uint((i4 & 1) ? tB : tA);
            tA = __shfl_sync(0xffffffffu, c2, srcLow);
            tB = __shfl_sync(0xffffffffu, c3, srcLow);
            uint32_t a1 = __float_as_uint((i4 & 1) ? tB : tA);
            tA = __shfl_sync(0xffffffffu, c0, srcHigh);
            tB = __shfl_sync(0xffffffffu, c1, srcHigh);
            uint32_t a2 = __float_as_uint((i4 & 1) ? tB : tA);
            tA = __shfl_sync(0xffffffffu, c2, srcHigh);
            tB = __shfl_sync(0xffffffffu, c3, srcHigh);
            uint32_t a3 = __float_as_uint((i4 & 1) ? tB : tA);

            const int r0 = ks * 8 + i4, r1 = ks * 8 + i4 + 4;
            #pragma unroll
            for (int nt = 0; nt < 16; nt++) {
                int c4v = nt * 2 + (g >> 2);
                uint32_t b0 = sVu[r0 * 128 + ((c4v ^ i4) << 2) + (g & 3)];
                uint32_t b1 = sVu[r1 * 128 + ((c4v ^ (i4 + 4)) << 2) + (g & 3)];
                float* c = o[nt];
                asm volatile(
                    "mma.sync.aligned.m16n8k8.row.col.f32.tf32.tf32.f32 "
                    "{%0,%1,%2,%3}, {%4,%5,%6,%7}, {%8,%9}, {%0,%1,%2,%3};\n"
                    : "+f"(c[0]), "+f"(c[1]), "+f"(c[2]), "+f"(c[3])
                    : "r"(a0), "r"(a1), "r"(a2), "r"(a3), "r"(b0), "r"(b1));
            }
        }
    }

    // ---- epilogue: normalize, round, write ctx [b,s][h*128+dh]
    float inv0 = 1.0f / l0, inv1 = 1.0f / l1;
    long row0 = (long)b * NS + qb * 128 + w * 16 + g;
    long row1 = row0 + 8;
    #pragma unroll
    for (int nt = 0; nt < 16; nt++) {
        int col = h * DH + nt * 8 + 2 * i4;
        float v0 = round_tf32f(o[nt][0] * inv0);
        float v1 = round_tf32f(o[nt][1] * inv0);
        float v2 = round_tf32f(o[nt][2] * inv1);
        float v3 = round_tf32f(o[nt][3] * inv1);
        *(float2*)(ctx + row0 * D + col) = make_float2(v0, v1);
        *(float2*)(ctx + row1 * D + col) = make_float2(v2, v3);
    }
}

// ---------------- launch ------------------------------------------------------
extern "C" void kernel_launch(void* const* d_in, const int* in_sizes, int n_in,
                              void* d_out, int out_size)
{
    const float* x     = (const float*)d_in[0];   // [4,1024,2048]
    const int*   ids   = (const int*)  d_in[1];   // [4,1024]
    const float* w_in  = (const float*)d_in[2];   // [6144,2048]
    const float* w_out = (const float*)d_in[3];   // [2048,2048]
    const float* b_out = (const float*)d_in[4];   // [2048]
    float* out = (float*)d_out;                   // [4,1024,2048]

    void *p_qkv, *p_ctx, *p_xr, *p_winr, *p_woutr;
    cudaGetSymbolAddress(&p_qkv,   g_qkv);
    cudaGetSymbolAddress(&p_ctx,   g_ctx);
    cudaGetSymbolAddress(&p_xr,    g_xr);
    cudaGetSymbolAddress(&p_winr,  g_winr);
    cudaGetSymbolAddress(&p_woutr, g_woutr);
    float* qkv   = (float*)p_qkv;
    float* ctx   = (float*)p_ctx;
    float* xr    = (float*)p_xr;
    float* winr  = (float*)p_winr;
    float* woutr = (float*)p_woutr;

    cudaFuncSetAttribute(tgemm_kernel<0, true>,
                         cudaFuncAttributeMaxDynamicSharedMemorySize, SMEM_BYTES);
    cudaFuncSetAttribute(tgemm_kernel<1, false>,
                         cudaFuncAttributeMaxDynamicSharedMemorySize, SMEM_BYTES);
    cudaFuncSetAttribute(flash_kernel,
                         cudaFuncAttributeMaxDynamicSharedMemorySize, FL_SMEM_BYTES);

    // K0: pre-round x, w_in, w_out to tf32
    round_tf32_kernel<<<512, 256>>>(x,     xr,    (long)SEQ * D / 4);
    round_tf32_kernel<<<512, 256>>>(w_in,  winr,  (long)E3 * D / 4);
    round_tf32_kernel<<<512, 256>>>(w_out, woutr, (long)D * D / 4);

    // K1: QKV = x @ w_in^T  (tf32-rounded output)
    tgemm_kernel<0, true><<<dim3(E3 / BN, SEQ / BM, 1), 256, SMEM_BYTES>>>(
        xr, winr, qkv, D, D, D, E3, nullptr);

    // K2: fused attention (QK^T + mask*scale + softmax + PV) -> ctx
    flash_kernel<<<dim3(NS / 128, BSZ * H), 256, FL_SMEM_BYTES>>>(qkv, ids, ctx);

    // K3: out = ctx @ w_out^T + b_out
    tgemm_kernel<1, false><<<dim3(D / BN, SEQ / BM, 1), 256, SMEM_BYTES>>>(
        ctx, woutr, out, D, D, D, D, b_out);
}